// round 11
// baseline (speedup 1.0000x reference)
#include <cuda_runtime.h>
#include <math_constants.h>

#define BB 4
#define PP 64
#define VV 32
#define DD 256

#define MARGIN 0.1f
#define L_PERM 1.0f
#define L_REG 0.1f
#define L_SIGMA 0.05f

#define NBLOCKS (BB * PP)   // 256: one block per (b, g)
#define NTHREADS 512        // 2 v-parities x 4 rotation slices x 64 preds

// Device scratch (no allocations allowed)
__device__ float g_costs[BB * PP * PP];
__device__ float g_reg[BB * PP];
__device__ float g_sig[BB * PP];
__device__ unsigned int g_counter[BB] = {0, 0, 0, 0};

// K rotation partial-accumulators at stride 4 (r = s + 4k) over v = h, h+2, ...
// (parity split -> both halves do ceil(mn/2) iterations, always balanced).
template <int K>
__device__ __forceinline__ void poly_part(int s, int h, int mn, int p,
                                          const float2* __restrict__ gtd,
                                          const float2 (*__restrict__ prs)[PP + 1],
                                          float (*__restrict__ part)[PP + 1])
{
    float sx[K], sy[K];
    #pragma unroll
    for (int k = 0; k < K; k++) { sx[k] = 0.0f; sy[k] = 0.0f; }

    #pragma unroll 2
    for (int v = h; v < mn; v += 2) {
        float2 q = prs[v][p];
        #pragma unroll
        for (int k = 0; k < K; k++) {
            float2 a = gtd[s + 4 * k + v];   // warp-uniform -> broadcast
            sx[k] += fabsf(a.x - q.x);
            sy[k] += fabsf(a.y - q.y);
        }
    }
    #pragma unroll
    for (int k = 0; k < K; k++)
        part[s + 4 * k][p] = sx[k] + sy[k]; // rows r >= nvg hold garbage (ignored)
}

__global__ void __launch_bounds__(NTHREADS)
fused_kernel(const float* __restrict__ gt,
             const float* __restrict__ pred,
             const float* __restrict__ mu,
             const float* __restrict__ sigma,
             const int*   __restrict__ mask,
             const int*   __restrict__ cls,
             float* __restrict__ out)
{
    const int b = blockIdx.x >> 6;
    const int g = blockIdx.x & 63;
    const int tid = threadIdx.x;           // 0..511
    const int h  = tid >> 8;               // v-parity 0/1
    const int rem = tid & 255;
    const int s  = rem >> 6;               // rotation slice 0..3
    const int p  = rem & 63;               // pred index

    __shared__ float2 gt_s[VV];
    __shared__ float2 gt_dup[2 * VV];      // gt[k % nvg]
    __shared__ float2 pred_s[VV][PP + 1];  // padded
    __shared__ int    nv_s[PP];
    __shared__ float  part_s[2][VV][PP + 1]; // per-(parity, rotation, p) partials
    __shared__ float  red_s[16];           // warps 0-7: mu^2, 8-15: 1/sigma
    __shared__ int    is_last_s;
    __shared__ float  cost_sh[PP][PP + 1]; // phase-2 staging (padded)

    // Issue cls early (L2-hot, off critical path)
    const bool is_poly = (cls[b * PP + g] == 1);

    // ---- reg/sig partials: mu on threads 0-255, sigma on 256-511 ----
    {
        const size_t base = ((size_t)b * PP + g) * DD;
        float acc;
        if (tid < DD) {
            float m = mu[base + tid];
            acc = m * m;
        } else {
            acc = 1.0f / sigma[base + tid - DD];
        }
        #pragma unroll
        for (int o = 16; o > 0; o >>= 1)
            acc += __shfl_down_sync(0xffffffffu, acc, o);
        if ((tid & 31) == 0) red_s[tid >> 5] = acc;
    }

    // ---- load gt row for this g ----
    if (tid < VV) {
        const float2* gt2 = (const float2*)(gt + ((size_t)b * PP + g) * VV * 2);
        gt_s[tid] = gt2[tid];
    }

    // ---- load pred tile, transposed + padded ----
    const float2* pr2 = (const float2*)(pred + (size_t)b * PP * VV * 2);
    #pragma unroll
    for (int k = 0; k < PP * VV / NTHREADS; k++) {
        int i = tid + k * NTHREADS;
        pred_s[i & 31][i >> 5] = pr2[i];
    }

    // ---- nv counts (one thread per pred row) ----
    if (tid < PP) {
        const int4* mrow = (const int4*)(mask + ((size_t)b * PP + tid) * VV);
        int cnt = 0;
        #pragma unroll
        for (int k = 0; k < VV / 4; k++) {
            int4 m4 = mrow[k];
            cnt += (m4.x == 0) + (m4.y == 0) + (m4.z == 0) + (m4.w == 0);
        }
        nv_s[tid] = cnt;
    }
    __syncthreads();

    const int nvg = nv_s[g];
    const int mn  = min(nvg, nv_s[p]);

    // ---- doubled gt table (entries >= 2*nvg finite garbage, masked later) ----
    if (tid < 2 * VV) {
        const int nn = max(nvg, 1);
        int j = (tid < nn) ? tid : (tid - nn);
        if (j >= nn) j -= nn;
        if (j >= nn) j = 0;
        gt_dup[tid] = gt_s[j];
    }
    __syncthreads();

    // ---- per-(parity, rotation-slice) partial sums ----
    if (is_poly) {
        const int kq = (nvg + 3) >> 2;     // ceil(nvg/4), block-uniform
        if (kq <= 2)      poly_part<2>(s, h, mn, p, gt_dup, pred_s, part_s[h]);
        else if (kq <= 4) poly_part<4>(s, h, mn, p, gt_dup, pred_s, part_s[h]);
        else if (kq <= 6) poly_part<6>(s, h, mn, p, gt_dup, pred_s, part_s[h]);
        else              poly_part<8>(s, h, mn, p, gt_dup, pred_s, part_s[h]);
    } else if (s < 2) {
        float sx = 0.0f, sy = 0.0f;
        #pragma unroll 2
        for (int v = h; v < mn; v += 2) {
            float2 q = pred_s[v][p];
            float2 a = (s == 0) ? gt_s[v] : gt_s[VV - 1 - v];
            sx += fabsf(a.x - q.x);
            sy += fabsf(a.y - q.y);
        }
        part_s[h][s][p] = sx + sy;
    }
    __syncthreads();

    // ---- combine parities, min over valid rotations, write cost row ----
    if (tid < PP) {
        const int rmax = is_poly ? nvg : 2;
        float c = CUDART_INF_F;
        for (int r = 0; r < rmax; r++)
            c = fminf(c, part_s[0][r][tid] + part_s[1][r][tid]);
        g_costs[((size_t)b * PP + g) * PP + tid] =
            c / (2.0f * (float)min(nvg, nv_s[tid]));
    }
    if (tid == 0) {
        float sm = 0.0f, ss = 0.0f;
        #pragma unroll
        for (int w = 0; w < 8; w++) { sm += red_s[w]; ss += red_s[8 + w]; }
        g_reg[b * PP + g] = sm;
        g_sig[b * PP + g] = ss;
    }

    // ---- elect last block OF THIS BATCH (64 blocks per batch) ----
    __syncthreads();
    if (tid == 0) {
        __threadfence();                   // release block's writes, one thread
        unsigned int v = atomicAdd(&g_counter[b], 1u);
        is_last_s = (v == PP - 1);
    }
    __syncthreads();
    if (!is_last_s) return;

    // ================= Phase 2: reduce batch b =================
    if (tid >= 256) return;
    __threadfence();                      // acquire: see peers' g_costs writes

    // Stage cost matrix coalesced into padded smem (256 thr x 16 floats)
    const float* Cb = g_costs + (size_t)b * PP * PP;
    #pragma unroll
    for (int k = 0; k < PP * PP / 256; k++) {
        int idx = k * 256 + tid;
        cost_sh[idx >> 6][idx & 63] = Cb[idx];
    }
    // Prefetch reg/sig partials
    float rv = 0.0f, sv = 0.0f;
    if (tid < PP) {
        rv = g_reg[b * PP + tid];
        sv = g_sig[b * PP + tid];
    }
    __syncthreads();

    if (tid >= PP) return;                // 64 threads remain
    const int ii = tid;
    const float dg = cost_sh[ii][ii];

    // Fused row+col hinge loop, all conflict-free LDS
    float mrow = 0.0f, mcol = 0.0f;
    int brk = 0;
    #pragma unroll 8
    for (int q = 0; q < PP; q++) {
        float cr = cost_sh[ii][q];         // costs[ii][q]
        float cc = cost_sh[q][ii];         // costs[q][ii]
        float dq = cost_sh[q][q];          // uniform -> broadcast
        if (q != ii) {
            mrow = fmaxf(mrow, fmaxf(MARGIN - cr + dg, 0.0f));
            mcol = fmaxf(mcol, fmaxf(MARGIN - cc + dg, 0.0f));
            brk |= ((cr < dg) & (cc < dq));
        }
    }

    float pv = mrow + mcol;
    #pragma unroll
    for (int o = 16; o > 0; o >>= 1) {
        pv += __shfl_down_sync(0xffffffffu, pv, o);
        rv += __shfl_down_sync(0xffffffffu, rv, o);
        sv += __shfl_down_sync(0xffffffffu, sv, o);
    }
    brk = __any_sync(0xffffffffu, brk);

    __shared__ float wsum2[2][3];
    __shared__ int   brk2[2];
    if ((tid & 31) == 0) {
        wsum2[tid >> 5][0] = pv;
        wsum2[tid >> 5][1] = rv;
        wsum2[tid >> 5][2] = sv;
        brk2[tid >> 5] = brk;
    }
    __syncthreads();

    if (tid == 0) {
        float perm = wsum2[0][0] + wsum2[1][0];
        float reg  = (wsum2[0][1] + wsum2[1][1]) / (float)PP;
        float sig  = (wsum2[0][2] + wsum2[1][2]) / (float)(PP * DD);
        float batch = L_REG * reg + L_SIGMA * sig + L_PERM * perm;
        out[b]          = batch;
        out[BB + b]     = perm;
        out[2 * BB + b] = reg;
        out[3 * BB + b] = sig;
        out[4 * BB + b] = (brk2[0] | brk2[1]) ? 1.0f : 0.0f;
        g_counter[b] = 0;                 // reset for next graph replay
    }
}

extern "C" void kernel_launch(void* const* d_in, const int* in_sizes, int n_in,
                              void* d_out, int out_size)
{
    const float* gt    = (const float*)d_in[0];
    const float* pred  = (const float*)d_in[1];
    const float* mu    = (const float*)d_in[2];
    const float* sigma = (const float*)d_in[3];
    const int*   mask  = (const int*)d_in[4];
    const int*   cls   = (const int*)d_in[5];
    float* out = (float*)d_out;

    fused_kernel<<<NBLOCKS, NTHREADS>>>(gt, pred, mu, sigma, mask, cls, out);
}

// round 12
// speedup vs baseline: 1.0173x; 1.0173x over previous
#include <cuda_runtime.h>
#include <math_constants.h>

#define BB 4
#define PP 64
#define VV 32
#define DD 256

#define MARGIN 0.1f
#define L_PERM 1.0f
#define L_REG 0.1f
#define L_SIGMA 0.05f

#define NBLOCKS (BB * PP)   // 256: one block per (b, g)
#define NTHREADS 512        // 2 v-parities x 4 rotation slices x 64 preds

// Device scratch (no allocations allowed)
__device__ float g_costs[BB * PP * PP];
__device__ float g_reg[BB * PP];
__device__ float g_sig[BB * PP];

// K rotation partial-accumulators at stride 4 (r = s + 4k) over v = h, h+2, ...
template <int K>
__device__ __forceinline__ void poly_part(int s, int h, int mn, int p,
                                          const float2* __restrict__ gtd,
                                          const float2 (*__restrict__ prs)[PP + 1],
                                          float (*__restrict__ part)[PP + 1])
{
    float sx[K], sy[K];
    #pragma unroll
    for (int k = 0; k < K; k++) { sx[k] = 0.0f; sy[k] = 0.0f; }

    #pragma unroll 2
    for (int v = h; v < mn; v += 2) {
        float2 q = prs[v][p];
        #pragma unroll
        for (int k = 0; k < K; k++) {
            float2 a = gtd[s + 4 * k + v];   // warp-uniform -> broadcast
            sx[k] += fabsf(a.x - q.x);
            sy[k] += fabsf(a.y - q.y);
        }
    }
    #pragma unroll
    for (int k = 0; k < K; k++)
        part[s + 4 * k][p] = sx[k] + sy[k]; // rows r >= nvg hold garbage (ignored)
}

// ---------------------------------------------------------------------------
// Kernel A: one block per (b, g). Costs + reg/sig partials. Two barriers.
// ---------------------------------------------------------------------------
__global__ void __launch_bounds__(NTHREADS)
costs_kernel(const float* __restrict__ gt,
             const float* __restrict__ pred,
             const float* __restrict__ mu,
             const float* __restrict__ sigma,
             const int*   __restrict__ mask,
             const int*   __restrict__ cls)
{
    const int b = blockIdx.x >> 6;
    const int g = blockIdx.x & 63;
    const int tid = threadIdx.x;           // 0..511
    const int h  = tid >> 8;               // v-parity 0/1
    const int rem = tid & 255;
    const int s  = rem >> 6;               // rotation slice 0..3
    const int p  = rem & 63;               // pred index

    __shared__ float2 gt_s[VV];
    __shared__ float2 gt_dup[2 * VV];      // gt[k % nvg]
    __shared__ float2 pred_s[VV][PP + 1];  // padded
    __shared__ int    nv_s[PP];
    __shared__ float  part_s[2][VV][PP + 1];
    __shared__ float  red_s[16];           // warps 0-7: mu^2, 8-15: 1/sigma

    const bool is_poly = (cls[b * PP + g] == 1);

    // ---- reg/sig partials: mu on threads 0-255, sigma on 256-511 ----
    {
        const size_t base = ((size_t)b * PP + g) * DD;
        float acc;
        if (tid < DD) {
            float m = mu[base + tid];
            acc = m * m;
        } else {
            acc = 1.0f / sigma[base + tid - DD];
        }
        #pragma unroll
        for (int o = 16; o > 0; o >>= 1)
            acc += __shfl_down_sync(0xffffffffu, acc, o);
        if ((tid & 31) == 0) red_s[tid >> 5] = acc;
    }

    // ---- warp 0: gt row + nvg (ballot) + gt_dup via shfl, all intra-warp ----
    if (tid < 32) {
        const float2* gt2 = (const float2*)(gt + ((size_t)b * PP + g) * VV * 2);
        float2 a = gt2[tid];
        gt_s[tid] = a;
        const int* mrow = mask + ((size_t)b * PP + g) * VV;
        unsigned bal = __ballot_sync(0xffffffffu, mrow[tid] == 0);
        int nn = max(__popc(bal), 1);
        int j1 = tid % nn;
        int j2 = (tid + 32) % nn;
        float2 d1, d2;
        d1.x = __shfl_sync(0xffffffffu, a.x, j1);
        d1.y = __shfl_sync(0xffffffffu, a.y, j1);
        d2.x = __shfl_sync(0xffffffffu, a.x, j2);
        d2.y = __shfl_sync(0xffffffffu, a.y, j2);
        gt_dup[tid] = d1;
        gt_dup[tid + 32] = d2;
    }

    // ---- pred tile, transposed + padded ----
    const float2* pr2 = (const float2*)(pred + (size_t)b * PP * VV * 2);
    #pragma unroll
    for (int k = 0; k < PP * VV / NTHREADS; k++) {
        int i = tid + k * NTHREADS;
        pred_s[i & 31][i >> 5] = pr2[i];
    }

    // ---- nv counts (one thread per pred row) ----
    if (tid < PP) {
        const int4* mrow = (const int4*)(mask + ((size_t)b * PP + tid) * VV);
        int cnt = 0;
        #pragma unroll
        for (int k = 0; k < VV / 4; k++) {
            int4 m4 = mrow[k];
            cnt += (m4.x == 0) + (m4.y == 0) + (m4.z == 0) + (m4.w == 0);
        }
        nv_s[tid] = cnt;
    }
    __syncthreads();                       // barrier 1

    const int nvg = nv_s[g];
    const int mn  = min(nvg, nv_s[p]);

    if (is_poly) {
        const int kq = (nvg + 3) >> 2;     // ceil(nvg/4), block-uniform
        if (kq <= 2)      poly_part<2>(s, h, mn, p, gt_dup, pred_s, part_s[h]);
        else if (kq <= 4) poly_part<4>(s, h, mn, p, gt_dup, pred_s, part_s[h]);
        else if (kq <= 6) poly_part<6>(s, h, mn, p, gt_dup, pred_s, part_s[h]);
        else              poly_part<8>(s, h, mn, p, gt_dup, pred_s, part_s[h]);
    } else if (s < 2) {
        float sx = 0.0f, sy = 0.0f;
        #pragma unroll 2
        for (int v = h; v < mn; v += 2) {
            float2 q = pred_s[v][p];
            float2 a = (s == 0) ? gt_s[v] : gt_s[VV - 1 - v];
            sx += fabsf(a.x - q.x);
            sy += fabsf(a.y - q.y);
        }
        part_s[h][s][p] = sx + sy;
    }
    __syncthreads();                       // barrier 2

    // ---- combine parities, min over valid rotations, write cost row ----
    if (tid < PP) {
        const int rmax = is_poly ? nvg : 2;
        float c = CUDART_INF_F;
        for (int r = 0; r < rmax; r++)
            c = fminf(c, part_s[0][r][tid] + part_s[1][r][tid]);
        g_costs[((size_t)b * PP + g) * PP + tid] =
            c / (2.0f * (float)min(nvg, nv_s[tid]));
    }
    if (tid == 0) {
        float sm = 0.0f, ss = 0.0f;
        #pragma unroll
        for (int w = 0; w < 8; w++) { sm += red_s[w]; ss += red_s[8 + w]; }
        g_reg[b * PP + g] = sm;
        g_sig[b * PP + g] = ss;
    }
}

// ---------------------------------------------------------------------------
// Kernel B: one block per batch; 256 threads. Final reduction.
// Output layout: [batch(4), perm(4), reg(4), sig(4), broken(4)] float32.
// ---------------------------------------------------------------------------
__global__ void __launch_bounds__(256)
reduce_kernel(float* __restrict__ out)
{
    const int b = blockIdx.x;
    const int tid = threadIdx.x;          // 0..255

    __shared__ float cost_sh[PP][PP + 1];
    __shared__ float wsum2[2][3];
    __shared__ int   brk2[2];

    // Stage cost matrix coalesced into padded smem (256 thr x 16 floats)
    const float* Cb = g_costs + (size_t)b * PP * PP;
    #pragma unroll
    for (int k = 0; k < PP * PP / 256; k++) {
        int idx = k * 256 + tid;
        cost_sh[idx >> 6][idx & 63] = Cb[idx];
    }
    // Prefetch reg/sig partials
    float rv = 0.0f, sv = 0.0f;
    if (tid < PP) {
        rv = g_reg[b * PP + tid];
        sv = g_sig[b * PP + tid];
    }
    __syncthreads();

    if (tid >= PP) return;                // 64 threads remain
    const int ii = tid;
    const float dg = cost_sh[ii][ii];

    // Fused row+col hinge loop, all conflict-free LDS
    float mrow = 0.0f, mcol = 0.0f;
    int brk = 0;
    #pragma unroll 8
    for (int q = 0; q < PP; q++) {
        float cr = cost_sh[ii][q];         // costs[ii][q]
        float cc = cost_sh[q][ii];         // costs[q][ii]
        float dq = cost_sh[q][q];          // uniform -> broadcast
        if (q != ii) {
            mrow = fmaxf(mrow, fmaxf(MARGIN - cr + dg, 0.0f));
            mcol = fmaxf(mcol, fmaxf(MARGIN - cc + dg, 0.0f));
            brk |= ((cr < dg) & (cc < dq));
        }
    }

    float pv = mrow + mcol;
    #pragma unroll
    for (int o = 16; o > 0; o >>= 1) {
        pv += __shfl_down_sync(0xffffffffu, pv, o);
        rv += __shfl_down_sync(0xffffffffu, rv, o);
        sv += __shfl_down_sync(0xffffffffu, sv, o);
    }
    brk = __any_sync(0xffffffffu, brk);

    if ((tid & 31) == 0) {
        wsum2[tid >> 5][0] = pv;
        wsum2[tid >> 5][1] = rv;
        wsum2[tid >> 5][2] = sv;
        brk2[tid >> 5] = brk;
    }
    __syncthreads();

    if (tid == 0) {
        float perm = wsum2[0][0] + wsum2[1][0];
        float reg  = (wsum2[0][1] + wsum2[1][1]) / (float)PP;
        float sig  = (wsum2[0][2] + wsum2[1][2]) / (float)(PP * DD);
        float batch = L_REG * reg + L_SIGMA * sig + L_PERM * perm;
        out[b]          = batch;
        out[BB + b]     = perm;
        out[2 * BB + b] = reg;
        out[3 * BB + b] = sig;
        out[4 * BB + b] = (brk2[0] | brk2[1]) ? 1.0f : 0.0f;
    }
}

extern "C" void kernel_launch(void* const* d_in, const int* in_sizes, int n_in,
                              void* d_out, int out_size)
{
    const float* gt    = (const float*)d_in[0];
    const float* pred  = (const float*)d_in[1];
    const float* mu    = (const float*)d_in[2];
    const float* sigma = (const float*)d_in[3];
    const int*   mask  = (const int*)d_in[4];
    const int*   cls   = (const int*)d_in[5];
    float* out = (float*)d_out;

    costs_kernel<<<NBLOCKS, NTHREADS>>>(gt, pred, mu, sigma, mask, cls);
    reduce_kernel<<<BB, 256>>>(out);
}

// round 13
// speedup vs baseline: 1.1572x; 1.1376x over previous
#include <cuda_runtime.h>
#include <math_constants.h>

#define BB 4
#define PP 64
#define VV 32
#define DD 256

#define MARGIN 0.1f
#define L_PERM 1.0f
#define L_REG 0.1f
#define L_SIGMA 0.05f

#define NBLOCKS (BB * PP)   // 256: one block per (b, g)
#define NTHREADS 512        // 2 v-parities x 4 rotation slices x 64 preds

// Device scratch (no allocations allowed)
__device__ float g_costs[BB * PP * PP];
__device__ float g_reg[BB * PP];
__device__ float g_sig[BB * PP];

// K rotation partial-accumulators at stride 4 (r = s + 4k) over v = h, h+2, ...
template <int K>
__device__ __forceinline__ void poly_part(int s, int h, int mn, int p,
                                          const float2* __restrict__ gtd,
                                          const float2 (*__restrict__ prs)[PP + 1],
                                          float (*__restrict__ part)[PP + 1])
{
    float sx[K], sy[K];
    #pragma unroll
    for (int k = 0; k < K; k++) { sx[k] = 0.0f; sy[k] = 0.0f; }

    #pragma unroll 2
    for (int v = h; v < mn; v += 2) {
        float2 q = prs[v][p];
        #pragma unroll
        for (int k = 0; k < K; k++) {
            float2 a = gtd[s + 4 * k + v];   // warp-uniform -> broadcast
            sx[k] += fabsf(a.x - q.x);
            sy[k] += fabsf(a.y - q.y);
        }
    }
    #pragma unroll
    for (int k = 0; k < K; k++)
        part[s + 4 * k][p] = sx[k] + sy[k]; // rows r >= nvg hold garbage (ignored)
}

// ---------------------------------------------------------------------------
// Kernel A: one block per (b, g). Costs + reg/sig partials. Two barriers.
// (verified round-12 version, unchanged)
// ---------------------------------------------------------------------------
__global__ void __launch_bounds__(NTHREADS)
costs_kernel(const float* __restrict__ gt,
             const float* __restrict__ pred,
             const float* __restrict__ mu,
             const float* __restrict__ sigma,
             const int*   __restrict__ mask,
             const int*   __restrict__ cls)
{
    const int b = blockIdx.x >> 6;
    const int g = blockIdx.x & 63;
    const int tid = threadIdx.x;           // 0..511
    const int h  = tid >> 8;               // v-parity 0/1
    const int rem = tid & 255;
    const int s  = rem >> 6;               // rotation slice 0..3
    const int p  = rem & 63;               // pred index

    __shared__ float2 gt_s[VV];
    __shared__ float2 gt_dup[2 * VV];      // gt[k % nvg]
    __shared__ float2 pred_s[VV][PP + 1];  // padded
    __shared__ int    nv_s[PP];
    __shared__ float  part_s[2][VV][PP + 1];
    __shared__ float  red_s[16];           // warps 0-7: mu^2, 8-15: 1/sigma

    const bool is_poly = (cls[b * PP + g] == 1);

    // ---- reg/sig partials: mu on threads 0-255, sigma on 256-511 ----
    {
        const size_t base = ((size_t)b * PP + g) * DD;
        float acc;
        if (tid < DD) {
            float m = mu[base + tid];
            acc = m * m;
        } else {
            acc = 1.0f / sigma[base + tid - DD];
        }
        #pragma unroll
        for (int o = 16; o > 0; o >>= 1)
            acc += __shfl_down_sync(0xffffffffu, acc, o);
        if ((tid & 31) == 0) red_s[tid >> 5] = acc;
    }

    // ---- warp 0: gt row + nvg (ballot) + gt_dup via shfl, all intra-warp ----
    if (tid < 32) {
        const float2* gt2 = (const float2*)(gt + ((size_t)b * PP + g) * VV * 2);
        float2 a = gt2[tid];
        gt_s[tid] = a;
        const int* mrow = mask + ((size_t)b * PP + g) * VV;
        unsigned bal = __ballot_sync(0xffffffffu, mrow[tid] == 0);
        int nn = max(__popc(bal), 1);
        int j1 = tid % nn;
        int j2 = (tid + 32) % nn;
        float2 d1, d2;
        d1.x = __shfl_sync(0xffffffffu, a.x, j1);
        d1.y = __shfl_sync(0xffffffffu, a.y, j1);
        d2.x = __shfl_sync(0xffffffffu, a.x, j2);
        d2.y = __shfl_sync(0xffffffffu, a.y, j2);
        gt_dup[tid] = d1;
        gt_dup[tid + 32] = d2;
    }

    // ---- pred tile, transposed + padded ----
    const float2* pr2 = (const float2*)(pred + (size_t)b * PP * VV * 2);
    #pragma unroll
    for (int k = 0; k < PP * VV / NTHREADS; k++) {
        int i = tid + k * NTHREADS;
        pred_s[i & 31][i >> 5] = pr2[i];
    }

    // ---- nv counts (one thread per pred row) ----
    if (tid < PP) {
        const int4* mrow = (const int4*)(mask + ((size_t)b * PP + tid) * VV);
        int cnt = 0;
        #pragma unroll
        for (int k = 0; k < VV / 4; k++) {
            int4 m4 = mrow[k];
            cnt += (m4.x == 0) + (m4.y == 0) + (m4.z == 0) + (m4.w == 0);
        }
        nv_s[tid] = cnt;
    }
    __syncthreads();                       // barrier 1

    const int nvg = nv_s[g];
    const int mn  = min(nvg, nv_s[p]);

    if (is_poly) {
        const int kq = (nvg + 3) >> 2;     // ceil(nvg/4), block-uniform
        if (kq <= 2)      poly_part<2>(s, h, mn, p, gt_dup, pred_s, part_s[h]);
        else if (kq <= 4) poly_part<4>(s, h, mn, p, gt_dup, pred_s, part_s[h]);
        else if (kq <= 6) poly_part<6>(s, h, mn, p, gt_dup, pred_s, part_s[h]);
        else              poly_part<8>(s, h, mn, p, gt_dup, pred_s, part_s[h]);
    } else if (s < 2) {
        float sx = 0.0f, sy = 0.0f;
        #pragma unroll 2
        for (int v = h; v < mn; v += 2) {
            float2 q = pred_s[v][p];
            float2 a = (s == 0) ? gt_s[v] : gt_s[VV - 1 - v];
            sx += fabsf(a.x - q.x);
            sy += fabsf(a.y - q.y);
        }
        part_s[h][s][p] = sx + sy;
    }
    __syncthreads();                       // barrier 2

    // ---- combine parities, min over valid rotations, write cost row ----
    if (tid < PP) {
        const int rmax = is_poly ? nvg : 2;
        float c = CUDART_INF_F;
        for (int r = 0; r < rmax; r++)
            c = fminf(c, part_s[0][r][tid] + part_s[1][r][tid]);
        g_costs[((size_t)b * PP + g) * PP + tid] =
            c / (2.0f * (float)min(nvg, nv_s[tid]));
    }
    if (tid == 0) {
        float sm = 0.0f, ss = 0.0f;
        #pragma unroll
        for (int w = 0; w < 8; w++) { sm += red_s[w]; ss += red_s[8 + w]; }
        g_reg[b * PP + g] = sm;
        g_sig[b * PP + g] = ss;
    }
}

// ---------------------------------------------------------------------------
// Kernel B: one block per batch; 256 threads, ALL kept live:
// thread (q4, ii) handles q in [16*q4, 16*q4+16) of row/col ii. Serial hinge
// depth 64 -> 16; partials combined by 64 threads.
// Output layout: [batch(4), perm(4), reg(4), sig(4), broken(4)] float32.
// ---------------------------------------------------------------------------
__global__ void __launch_bounds__(256)
reduce_kernel(float* __restrict__ out)
{
    const int b = blockIdx.x;
    const int tid = threadIdx.x;          // 0..255
    const int q4 = tid >> 6;              // q-quarter 0..3
    const int ii = tid & 63;              // row/col index

    __shared__ float cost_sh[PP][PP + 1];
    __shared__ float pr_row[4][PP + 1];   // per-quarter row-hinge partials
    __shared__ float pr_col[4][PP + 1];   // per-quarter col-hinge partials
    __shared__ int   pr_brk[4][PP + 1];
    __shared__ float wsum2[2][3];
    __shared__ int   brk2[2];

    // Stage cost matrix coalesced into padded smem (256 thr x 16 floats)
    const float* Cb = g_costs + (size_t)b * PP * PP;
    #pragma unroll
    for (int k = 0; k < PP * PP / 256; k++) {
        int idx = k * 256 + tid;
        cost_sh[idx >> 6][idx & 63] = Cb[idx];
    }
    // Prefetch reg/sig partials
    float rv = 0.0f, sv = 0.0f;
    if (tid < PP) {
        rv = g_reg[b * PP + tid];
        sv = g_sig[b * PP + tid];
    }
    __syncthreads();

    // Quarter hinge loop: 16 iterations, all conflict-free LDS
    const float dg = cost_sh[ii][ii];
    float mrow = 0.0f, mcol = 0.0f;
    int brk = 0;
    const int q0 = q4 * 16;
    #pragma unroll 16
    for (int t = 0; t < 16; t++) {
        int q = q0 + t;
        float cr = cost_sh[ii][q];         // costs[ii][q]
        float cc = cost_sh[q][ii];         // costs[q][ii]
        float dq = cost_sh[q][q];
        if (q != ii) {
            mrow = fmaxf(mrow, fmaxf(MARGIN - cr + dg, 0.0f));
            mcol = fmaxf(mcol, fmaxf(MARGIN - cc + dg, 0.0f));
            brk |= ((cr < dg) & (cc < dq));
        }
    }
    pr_row[q4][ii] = mrow;
    pr_col[q4][ii] = mcol;
    pr_brk[q4][ii] = brk;
    __syncthreads();

    if (tid >= PP) return;                // 64 threads combine

    float fr = fmaxf(fmaxf(pr_row[0][ii], pr_row[1][ii]),
                     fmaxf(pr_row[2][ii], pr_row[3][ii]));
    float fc = fmaxf(fmaxf(pr_col[0][ii], pr_col[1][ii]),
                     fmaxf(pr_col[2][ii], pr_col[3][ii]));
    int fb = pr_brk[0][ii] | pr_brk[1][ii] | pr_brk[2][ii] | pr_brk[3][ii];

    float pv = fr + fc;
    #pragma unroll
    for (int o = 16; o > 0; o >>= 1) {
        pv += __shfl_down_sync(0xffffffffu, pv, o);
        rv += __shfl_down_sync(0xffffffffu, rv, o);
        sv += __shfl_down_sync(0xffffffffu, sv, o);
    }
    fb = __any_sync(0xffffffffu, fb);

    if ((tid & 31) == 0) {
        wsum2[tid >> 5][0] = pv;
        wsum2[tid >> 5][1] = rv;
        wsum2[tid >> 5][2] = sv;
        brk2[tid >> 5] = fb;
    }
    __syncthreads();

    if (tid == 0) {
        float perm = wsum2[0][0] + wsum2[1][0];
        float reg  = (wsum2[0][1] + wsum2[1][1]) / (float)PP;
        float sig  = (wsum2[0][2] + wsum2[1][2]) / (float)(PP * DD);
        float batch = L_REG * reg + L_SIGMA * sig + L_PERM * perm;
        out[b]          = batch;
        out[BB + b]     = perm;
        out[2 * BB + b] = reg;
        out[3 * BB + b] = sig;
        out[4 * BB + b] = (brk2[0] | brk2[1]) ? 1.0f : 0.0f;
    }
}

extern "C" void kernel_launch(void* const* d_in, const int* in_sizes, int n_in,
                              void* d_out, int out_size)
{
    const float* gt    = (const float*)d_in[0];
    const float* pred  = (const float*)d_in[1];
    const float* mu    = (const float*)d_in[2];
    const float* sigma = (const float*)d_in[3];
    const int*   mask  = (const int*)d_in[4];
    const int*   cls   = (const int*)d_in[5];
    float* out = (float*)d_out;

    costs_kernel<<<NBLOCKS, NTHREADS>>>(gt, pred, mu, sigma, mask, cls);
    reduce_kernel<<<BB, 256>>>(out);
}

// round 14
// speedup vs baseline: 1.1864x; 1.0252x over previous
#include <cuda_runtime.h>
#include <math_constants.h>

#define BB 4
#define PP 64
#define VV 32
#define DD 256

#define MARGIN 0.1f
#define L_PERM 1.0f
#define L_REG 0.1f
#define L_SIGMA 0.05f

#define NBLOCKS (BB * PP)   // 256: one block per (b, g)
#define NTHREADS 512        // 2 v-parities x 4 rotation slices x 64 preds

// Device scratch (no allocations allowed; all zero-init semantics respected)
__device__ float    g_diag[BB * PP];
__device__ float    g_rowh[BB * PP];
__device__ int      g_colkey[BB * PP];   // stores INT_MAX - as_int(c); 0 == +inf
__device__ unsigned g_ar[BB * PP * 2];   // broken bitmask, 2x u32 per row
__device__ float    g_reg[BB * PP];
__device__ float    g_sig[BB * PP];
__device__ unsigned g_counter[BB] = {0, 0, 0, 0};

// K rotation partial-accumulators at stride 4 (r = s + 4k) over v = h, h+2, ...
template <int K>
__device__ __forceinline__ void poly_part(int s, int h, int mn, int p,
                                          const float2* __restrict__ gtd,
                                          const float2 (*__restrict__ prs)[PP + 1],
                                          float (*__restrict__ part)[PP + 1])
{
    float sx[K], sy[K];
    #pragma unroll
    for (int k = 0; k < K; k++) { sx[k] = 0.0f; sy[k] = 0.0f; }

    #pragma unroll 2
    for (int v = h; v < mn; v += 2) {
        float2 q = prs[v][p];
        #pragma unroll
        for (int k = 0; k < K; k++) {
            float2 a = gtd[s + 4 * k + v];   // warp-uniform -> broadcast
            sx[k] += fabsf(a.x - q.x);
            sy[k] += fabsf(a.y - q.y);
        }
    }
    #pragma unroll
    for (int k = 0; k < K; k++)
        part[s + 4 * k][p] = sx[k] + sy[k]; // rows r >= nvg hold garbage (ignored)
}

__global__ void __launch_bounds__(NTHREADS)
fused_kernel(const float* __restrict__ gt,
             const float* __restrict__ pred,
             const float* __restrict__ mu,
             const float* __restrict__ sigma,
             const int*   __restrict__ mask,
             const int*   __restrict__ cls,
             float* __restrict__ out)
{
    const int b = blockIdx.x >> 6;
    const int g = blockIdx.x & 63;
    const int tid = threadIdx.x;           // 0..511
    const int h  = tid >> 8;               // v-parity 0/1
    const int rem = tid & 255;
    const int s  = rem >> 6;               // rotation slice 0..3
    const int p  = rem & 63;               // pred index

    __shared__ float2 gt_s[VV];
    __shared__ float2 gt_dup[2 * VV];
    __shared__ float2 pred_s[VV][PP + 1];
    __shared__ int    nv_s[PP];
    __shared__ float  part_s[2][VV][PP + 1];
    __shared__ float  red_s[16];           // warps 0-7: mu^2, 8-15: 1/sigma
    __shared__ float  cost_row[PP];
    __shared__ float  rm_sh[2];
    __shared__ int    is_last_s;

    const bool is_poly = (cls[b * PP + g] == 1);

    // ---- reg/sig partials: mu on threads 0-255, sigma on 256-511 ----
    {
        const size_t base = ((size_t)b * PP + g) * DD;
        float acc;
        if (tid < DD) {
            float m = mu[base + tid];
            acc = m * m;
        } else {
            acc = 1.0f / sigma[base + tid - DD];
        }
        #pragma unroll
        for (int o = 16; o > 0; o >>= 1)
            acc += __shfl_down_sync(0xffffffffu, acc, o);
        if ((tid & 31) == 0) red_s[tid >> 5] = acc;
    }

    // ---- warp 0: gt row + nvg (ballot) + gt_dup via shfl, all intra-warp ----
    if (tid < 32) {
        const float2* gt2 = (const float2*)(gt + ((size_t)b * PP + g) * VV * 2);
        float2 a = gt2[tid];
        gt_s[tid] = a;
        const int* mrow = mask + ((size_t)b * PP + g) * VV;
        unsigned bal = __ballot_sync(0xffffffffu, mrow[tid] == 0);
        int nn = max(__popc(bal), 1);
        int j1 = tid % nn;
        int j2 = (tid + 32) % nn;
        float2 d1, d2;
        d1.x = __shfl_sync(0xffffffffu, a.x, j1);
        d1.y = __shfl_sync(0xffffffffu, a.y, j1);
        d2.x = __shfl_sync(0xffffffffu, a.x, j2);
        d2.y = __shfl_sync(0xffffffffu, a.y, j2);
        gt_dup[tid] = d1;
        gt_dup[tid + 32] = d2;
    }

    // ---- pred tile, transposed + padded ----
    const float2* pr2 = (const float2*)(pred + (size_t)b * PP * VV * 2);
    #pragma unroll
    for (int k = 0; k < PP * VV / NTHREADS; k++) {
        int i = tid + k * NTHREADS;
        pred_s[i & 31][i >> 5] = pr2[i];
    }

    // ---- nv counts (one thread per pred row) ----
    if (tid < PP) {
        const int4* mrow = (const int4*)(mask + ((size_t)b * PP + tid) * VV);
        int cnt = 0;
        #pragma unroll
        for (int k = 0; k < VV / 4; k++) {
            int4 m4 = mrow[k];
            cnt += (m4.x == 0) + (m4.y == 0) + (m4.z == 0) + (m4.w == 0);
        }
        nv_s[tid] = cnt;
    }
    __syncthreads();                       // barrier 1

    const int nvg = nv_s[g];
    const int mn  = min(nvg, nv_s[p]);

    if (is_poly) {
        const int kq = (nvg + 3) >> 2;     // ceil(nvg/4), block-uniform
        if (kq <= 2)      poly_part<2>(s, h, mn, p, gt_dup, pred_s, part_s[h]);
        else if (kq <= 4) poly_part<4>(s, h, mn, p, gt_dup, pred_s, part_s[h]);
        else if (kq <= 6) poly_part<6>(s, h, mn, p, gt_dup, pred_s, part_s[h]);
        else              poly_part<8>(s, h, mn, p, gt_dup, pred_s, part_s[h]);
    } else if (s < 2) {
        float sx = 0.0f, sy = 0.0f;
        #pragma unroll 2
        for (int v = h; v < mn; v += 2) {
            float2 q = pred_s[v][p];
            float2 a = (s == 0) ? gt_s[v] : gt_s[VV - 1 - v];
            sx += fabsf(a.x - q.x);
            sy += fabsf(a.y - q.y);
        }
        part_s[h][s][p] = sx + sy;
    }
    __syncthreads();                       // barrier 2

    // ---- combine parities, form this block's cost row ----
    float c = 0.0f;
    if (tid < PP) {
        const int rmax = is_poly ? nvg : 2;
        float cm = CUDART_INF_F;
        for (int r = 0; r < rmax; r++)
            cm = fminf(cm, part_s[0][r][tid] + part_s[1][r][tid]);
        c = cm / (2.0f * (float)min(nvg, nv_s[tid]));
        cost_row[tid] = c;
    }
    if (tid == 0) {
        float sm = 0.0f, ss = 0.0f;
        #pragma unroll
        for (int w = 0; w < 8; w++) { sm += red_s[w]; ss += red_s[8 + w]; }
        g_reg[b * PP + g] = sm;
        g_sig[b * PP + g] = ss;
    }
    __syncthreads();                       // barrier 3

    // ---- row-min, column-min contribution, broken bitmask ----
    if (tid < PP) {
        const float dgg = cost_row[g];
        // column-min: order-preserving key, zero-init == +inf, via atomicMax
        if (tid != g)
            atomicMax(&g_colkey[b * PP + tid], 0x7fffffff - __float_as_int(c));
        // broken bitmask: bit p = (c[g][p] < d_g) & (p != g)
        bool a = (c < dgg) && (tid != g);
        unsigned bal = __ballot_sync(0xffffffffu, a);
        if ((tid & 31) == 0) g_ar[(b * PP + g) * 2 + (tid >> 5)] = bal;
        // row-min over p != g
        float cv = (tid == g) ? CUDART_INF_F : c;
        #pragma unroll
        for (int o = 16; o > 0; o >>= 1)
            cv = fminf(cv, __shfl_down_sync(0xffffffffu, cv, o));
        if ((tid & 31) == 0) rm_sh[tid >> 5] = cv;
    }
    __syncthreads();                       // barrier 4
    if (tid == 0) {
        const float dgg = cost_row[g];
        float rmin = fminf(rm_sh[0], rm_sh[1]);
        g_rowh[b * PP + g] = fmaxf(0.0f, MARGIN + dgg - rmin);
        g_diag[b * PP + g] = dgg;
        __threadfence();                   // release this block's writes
        unsigned v = atomicAdd(&g_counter[b], 1u);
        is_last_s = (v == PP - 1);
    }
    __syncthreads();                       // barrier 5 (broadcast)
    if (!is_last_s) return;

    // ================= Phase 2: tiny reduction for batch b =================
    if (tid >= 256) return;
    __threadfence();                      // acquire: see peers' writes

    __shared__ unsigned long long ar_sh[PP];
    __shared__ float wsum2[2][3];

    if (tid < 128)
        ((unsigned*)ar_sh)[tid] = g_ar[b * PP * 2 + tid];

    float pv = 0.0f, rv = 0.0f, sv = 0.0f;
    if (tid < PP) {
        float d   = g_diag[b * PP + tid];
        int   key = g_colkey[b * PP + tid];
        float cmin = __int_as_float(0x7fffffff - key);
        float colh = fmaxf(0.0f, MARGIN + d - cmin);
        pv = g_rowh[b * PP + tid] + colh;
        rv = g_reg[b * PP + tid];
        sv = g_sig[b * PP + tid];
        g_colkey[b * PP + tid] = 0;        // reset (+inf) for next replay
    }
    __syncthreads();

    // broken: thread (q4, ii) checks 16 pairs via bitmask AND
    int brk = 0;
    {
        const int ii = tid & 63;
        const int q0 = (tid >> 6) * 16;
        unsigned long long my = ar_sh[ii];
        #pragma unroll 16
        for (int t = 0; t < 16; t++) {
            int q = q0 + t;
            brk |= (int)((my >> q) & (ar_sh[q] >> ii) & 1ULL);
        }
    }
    const int anybrk = __syncthreads_or(brk);

    if (tid < PP) {
        #pragma unroll
        for (int o = 16; o > 0; o >>= 1) {
            pv += __shfl_down_sync(0xffffffffu, pv, o);
            rv += __shfl_down_sync(0xffffffffu, rv, o);
            sv += __shfl_down_sync(0xffffffffu, sv, o);
        }
        if ((tid & 31) == 0) {
            wsum2[tid >> 5][0] = pv;
            wsum2[tid >> 5][1] = rv;
            wsum2[tid >> 5][2] = sv;
        }
    }
    __syncthreads();

    if (tid == 0) {
        float perm = wsum2[0][0] + wsum2[1][0];
        float reg  = (wsum2[0][1] + wsum2[1][1]) / (float)PP;
        float sig  = (wsum2[0][2] + wsum2[1][2]) / (float)(PP * DD);
        float batch = L_REG * reg + L_SIGMA * sig + L_PERM * perm;
        out[b]          = batch;
        out[BB + b]     = perm;
        out[2 * BB + b] = reg;
        out[3 * BB + b] = sig;
        out[4 * BB + b] = anybrk ? 1.0f : 0.0f;
        g_counter[b] = 0;                 // reset for next graph replay
    }
}

extern "C" void kernel_launch(void* const* d_in, const int* in_sizes, int n_in,
                              void* d_out, int out_size)
{
    const float* gt    = (const float*)d_in[0];
    const float* pred  = (const float*)d_in[1];
    const float* mu    = (const float*)d_in[2];
    const float* sigma = (const float*)d_in[3];
    const int*   mask  = (const int*)d_in[4];
    const int*   cls   = (const int*)d_in[5];
    float* out = (float*)d_out;

    fused_kernel<<<NBLOCKS, NTHREADS>>>(gt, pred, mu, sigma, mask, cls, out);
}